// round 12
// baseline (speedup 1.0000x reference)
#include <cuda_runtime.h>
#include <cuda_fp16.h>
#include <stdint.h>
#include <math.h>

// Problem constants (fixed by dataset)
#define Bsz  8
#define Qlen 2048
#define Klen 2048
#define Hdim 128
#define BM   64          // queries per CTA
#define BN   64          // keys per tile
#define NT   128         // 4 warps
#define NTILE (Klen / BN)

#define KTOT (Bsz * Klen * Hdim)   // 2,097,152 elements

// Pre-split history scratch (fp16 hi + residual lo), row-major [b][key][h]
__device__ __align__(16) __half g_khi[KTOT];
__device__ __align__(16) __half g_klo[KTOT];

// stage: [hi fp16 swizzled 16KB][lo fp16 swizzled 16KB]; double buffered = 64KB
#define TILE_HI_BYTES 16384
#define TILE_BYTES    32768
#define SMEM_BYTES    (2 * TILE_BYTES)

#define LOG2E 1.4426950408889634f
#define ONESF16X2 0x3C003C00u     // half2(1.0, 1.0)

__device__ __forceinline__ uint32_t smem_u32(const void* p) {
    uint32_t a;
    asm("{ .reg .u64 t; cvta.to.shared.u64 t, %1; cvt.u32.u64 %0, t; }" : "=r"(a) : "l"(p));
    return a;
}
__device__ __forceinline__ uint32_t h2u(__half2 h) { return *reinterpret_cast<uint32_t*>(&h); }
__device__ __forceinline__ float ex2f(float x) {
    float y; asm("ex2.approx.ftz.f32 %0, %1;" : "=f"(y) : "f"(x)); return y;
}
__device__ __forceinline__ uint32_t ex2h2(uint32_t x) {
    uint32_t y; asm("ex2.approx.f16x2 %0, %1;" : "=r"(y) : "r"(x)); return y;
}
// register-file 8x8 b16 transpose (no shared-memory traffic)
__device__ __forceinline__ uint32_t movm(uint32_t a) {
    uint32_t d;
    asm("movmatrix.sync.aligned.m8n8.trans.b16 %0, %1;" : "=r"(d) : "r"(a));
    return d;
}

// fp32 pair -> fp16 hi + fp16 residual(lo), packed half2
__device__ __forceinline__ void split_h2(float x, float y, uint32_t& hi, uint32_t& lo) {
    __half2 h = __floats2half2_rn(x, y);
    float rx = x - __half2float(__low2half(h));
    float ry = y - __half2float(__high2half(h));
    __half2 l = __floats2half2_rn(rx, ry);
    hi = h2u(h); lo = h2u(l);
}

// XOR-swizzled tile offset: row in [0,64), bytecol in [0,256)
__device__ __forceinline__ uint32_t swz2(int row, int bytecol) {
    int ch = bytecol >> 4;
    int chs = (ch & 8) | ((ch ^ row) & 7);
    return (uint32_t)(row * 256 + (chs << 4));
}

__device__ __forceinline__ void cpa16(uint32_t dst, const void* src) {
    asm volatile("cp.async.cg.shared.global [%0], [%1], 16;" :: "r"(dst), "l"(src));
}
#define CP_COMMIT() asm volatile("cp.async.commit_group;" ::: "memory")
#define CP_WAIT0()  asm volatile("cp.async.wait_group 0;" ::: "memory")

__device__ __forceinline__ void ldsm_x4(uint32_t& r0, uint32_t& r1, uint32_t& r2, uint32_t& r3,
                                        uint32_t addr) {
    asm volatile("ldmatrix.sync.aligned.m8n8.x4.shared.b16 {%0,%1,%2,%3}, [%4];"
                 : "=r"(r0), "=r"(r1), "=r"(r2), "=r"(r3) : "r"(addr));
}
// D(16x8,f32) += A(16x16,f16) * B(16x8,f16)
__device__ __forceinline__ void mma16816(float* d, const uint32_t* a, uint32_t b0, uint32_t b1) {
    asm volatile("mma.sync.aligned.m16n8k16.row.col.f32.f16.f16.f32 "
                 "{%0,%1,%2,%3}, {%4,%5,%6,%7}, {%8,%9}, {%0,%1,%2,%3};"
                 : "+f"(d[0]), "+f"(d[1]), "+f"(d[2]), "+f"(d[3])
                 : "r"(a[0]), "r"(a[1]), "r"(a[2]), "r"(a[3]), "r"(b0), "r"(b1));
}

// ---------------- Pre-pass: split history fp32 -> fp16 hi/lo ----------------
__global__ __launch_bounds__(256)
void prep_split(const float* __restrict__ history)
{
    const size_t i = ((size_t)blockIdx.x * 256 + threadIdx.x) * 8;
    float4 a = *(const float4*)(history + i);
    float4 b = *(const float4*)(history + i + 4);
    uint32_t h[4], l[4];
    split_h2(a.x, a.y, h[0], l[0]);
    split_h2(a.z, a.w, h[1], l[1]);
    split_h2(b.x, b.y, h[2], l[2]);
    split_h2(b.z, b.w, h[3], l[3]);
    *(uint4*)(g_khi + i) = make_uint4(h[0], h[1], h[2], h[3]);
    *(uint4*)(g_klo + i) = make_uint4(l[0], l[1], l[2], l[3]);
}

// ---------------- Main attention kernel ----------------
__global__ __launch_bounds__(NT, 2)
void attn_hmma(const float* __restrict__ out_state,
               float* __restrict__ out)
{
    extern __shared__ __align__(16) char smb[];
    const uint32_t s_base = smem_u32(smb);

    const int t    = threadIdx.x;
    const int wm   = t >> 5;          // warp id = query-row group
    const int lane = t & 31;
    const int g    = lane >> 2;       // row within fragment group (0..7)
    const int tc   = lane & 3;        // col pair within group
    const int q0   = blockIdx.x * BM;
    const int b    = blockIdx.y;

    const float*  q_g  = out_state + (size_t)b * Qlen * Hdim;
    const __half* khiB = g_khi + (size_t)b * Klen * Hdim;
    const __half* kloB = g_klo + (size_t)b * Klen * Hdim;
    float*        o_g  = out + (size_t)b * Qlen * Hdim;

    // ---- Q A-fragments: tanh * log2e, split fp16 hi/lo ----
    uint32_t qhi[8][4], qlo[8][4];
    {
        const float* qb = q_g + (size_t)(q0 + wm * 16 + g) * Hdim;
        #pragma unroll
        for (int kk = 0; kk < 8; ++kk) {
            const int h0 = kk * 16 + tc * 2;
            float2 x00 = *(const float2*)(qb + h0);
            float2 x10 = *(const float2*)(qb + 8 * Hdim + h0);
            float2 x01 = *(const float2*)(qb + h0 + 8);
            float2 x11 = *(const float2*)(qb + 8 * Hdim + h0 + 8);
            x00.x = tanhf(x00.x) * LOG2E; x00.y = tanhf(x00.y) * LOG2E;
            x10.x = tanhf(x10.x) * LOG2E; x10.y = tanhf(x10.y) * LOG2E;
            x01.x = tanhf(x01.x) * LOG2E; x01.y = tanhf(x01.y) * LOG2E;
            x11.x = tanhf(x11.x) * LOG2E; x11.y = tanhf(x11.y) * LOG2E;
            split_h2(x00.x, x00.y, qhi[kk][0], qlo[kk][0]);
            split_h2(x10.x, x10.y, qhi[kk][1], qlo[kk][1]);
            split_h2(x01.x, x01.y, qhi[kk][2], qlo[kk][2]);
            split_h2(x11.x, x11.y, qhi[kk][3], qlo[kk][3]);
        }
    }

    // O accumulator: 16 h-tiles x 4 f32 (rows g, g+8) + l-column (ones-MMA)
    float o[16][4];
    #pragma unroll
    for (int n = 0; n < 16; ++n)
        #pragma unroll
        for (int j = 0; j < 4; ++j) o[n][j] = 0.f;
    float ol[4] = {0.f, 0.f, 0.f, 0.f};

    float m0 = -INFINITY, m1 = -INFINITY;

    // ---- Prefetch tile 0 into buffer 0 ----
    {
        #pragma unroll
        for (int j = 0; j < 8; ++j) {
            const int idx = j * NT + t;        // 0..1023
            const int row = idx >> 4;
            const int ch  = idx & 15;
            const uint32_t d = s_base + swz2(row, ch << 4);
            cpa16(d,                 khiB + (size_t)row * Hdim + ch * 8);
            cpa16(d + TILE_HI_BYTES, kloB + (size_t)row * Hdim + ch * 8);
        }
        CP_COMMIT();
    }

    for (int kt = 0; kt < NTILE; ++kt) {
        CP_WAIT0();
        __syncthreads();   // tile kt visible; all warps done with the other buffer

        // ---- Prefetch tile kt+1 into the other buffer ----
        if (kt + 1 < NTILE) {
            const uint32_t sb = s_base + ((kt + 1) & 1) * TILE_BYTES;
            const __half* srcH = khiB + (size_t)(kt + 1) * BN * Hdim;
            const __half* srcL = kloB + (size_t)(kt + 1) * BN * Hdim;
            #pragma unroll
            for (int j = 0; j < 8; ++j) {
                const int idx = j * NT + t;
                const int row = idx >> 4;
                const int ch  = idx & 15;
                const uint32_t d = sb + swz2(row, ch << 4);
                cpa16(d,                 srcH + (size_t)row * Hdim + ch * 8);
                cpa16(d + TILE_HI_BYTES, srcL + (size_t)row * Hdim + ch * 8);
            }
            CP_COMMIT();
        }

        const uint32_t s_hi = s_base + (kt & 1) * TILE_BYTES;
        const uint32_t s_lo = s_hi + TILE_HI_BYTES;

        // ==== stream four 16-key chunks: QK -> softmax -> PV(movmatrix) ====
        #pragma unroll
        for (int np = 0; np < 4; ++np) {
            // ---- QK chunk: S (16 queries x 16 keys), 3-pass split ----
            uint32_t bh[8][4];     // K-hi fragments, kept live for PV reuse
            float s[2][4];
            s[0][0]=0.f; s[0][1]=0.f; s[0][2]=0.f; s[0][3]=0.f;
            s[1][0]=0.f; s[1][1]=0.f; s[1][2]=0.f; s[1][3]=0.f;

            const int rowb = np * 16 + (lane & 7) + ((lane >> 4) << 3);
            #pragma unroll
            for (int kk = 0; kk < 8; ++kk) {
                const int col = kk * 32 + ((lane >> 3) & 1) * 16;   // bytes
                uint32_t bl0, bl1, bl2, bl3;
                ldsm_x4(bh[kk][0], bh[kk][1], bh[kk][2], bh[kk][3], s_hi + swz2(rowb, col));
                ldsm_x4(bl0, bl1, bl2, bl3,                         s_lo + swz2(rowb, col));
                mma16816(s[0], qhi[kk], bh[kk][0], bh[kk][1]);
                mma16816(s[1], qhi[kk], bh[kk][2], bh[kk][3]);
                mma16816(s[0], qhi[kk], bl0, bl1);
                mma16816(s[1], qhi[kk], bl2, bl3);
                mma16816(s[0], qlo[kk], bh[kk][0], bh[kk][1]);
                mma16816(s[1], qlo[kk], bh[kk][2], bh[kk][3]);
            }

            // ---- softmax chunk (base-2 online; warp-local rows) ----
            float t0 = fmaxf(fmaxf(s[0][0], s[0][1]), fmaxf(s[1][0], s[1][1]));
            float t1 = fmaxf(fmaxf(s[0][2], s[0][3]), fmaxf(s[1][2], s[1][3]));
            t0 = fmaxf(t0, __shfl_xor_sync(0xffffffffu, t0, 1));
            t0 = fmaxf(t0, __shfl_xor_sync(0xffffffffu, t0, 2));
            t1 = fmaxf(t1, __shfl_xor_sync(0xffffffffu, t1, 1));
            t1 = fmaxf(t1, __shfl_xor_sync(0xffffffffu, t1, 2));

            const float mn0 = fmaxf(m0, t0), mn1 = fmaxf(m1, t1);
            const bool updated = (mn0 != m0) | (mn1 != m1);
            const bool any_up  = __any_sync(0xffffffffu, updated);
            const float al0 = ex2f(m0 - mn0), al1 = ex2f(m1 - mn1);
            m0 = mn0; m1 = mn1;

            uint32_t pa[4];
            pa[0] = ex2h2(h2u(__floats2half2_rn(s[0][0] - mn0, s[0][1] - mn0)));
            pa[1] = ex2h2(h2u(__floats2half2_rn(s[0][2] - mn1, s[0][3] - mn1)));
            pa[2] = ex2h2(h2u(__floats2half2_rn(s[1][0] - mn0, s[1][1] - mn0)));
            pa[3] = ex2h2(h2u(__floats2half2_rn(s[1][2] - mn1, s[1][3] - mn1)));

            if (any_up) {
                #pragma unroll
                for (int n = 0; n < 16; ++n) {
                    o[n][0] *= al0; o[n][1] *= al0;
                    o[n][2] *= al1; o[n][3] *= al1;
                }
                ol[0] *= al0; ol[1] *= al0; ol[2] *= al1; ol[3] *= al1;
            }

            // ---- PV chunk: V-fragments via register transpose of bh (no smem!) ----
            #pragma unroll
            for (int kk = 0; kk < 8; ++kk) {
                mma16816(o[2*kk],     pa, movm(bh[kk][0]), movm(bh[kk][2]));
                mma16816(o[2*kk + 1], pa, movm(bh[kk][1]), movm(bh[kk][3]));
            }
            mma16816(ol, pa, ONESF16X2, ONESF16X2);   // row sums -> l
        }
    }

    // ---- Epilogue: normalize by l and store ----
    const float inv0 = 1.0f / ol[0];
    const float inv1 = 1.0f / ol[2];
    float* ob = o_g + (size_t)(q0 + wm * 16 + g) * Hdim;
    #pragma unroll
    for (int n = 0; n < 16; ++n) {
        const int h = n * 8 + tc * 2;
        *(float2*)(ob + h)            = make_float2(o[n][0] * inv0, o[n][1] * inv0);
        *(float2*)(ob + 8 * Hdim + h) = make_float2(o[n][2] * inv1, o[n][3] * inv1);
    }
}

extern "C" void kernel_launch(void* const* d_in, const int* in_sizes, int n_in,
                              void* d_out, int out_size)
{
    const float* out_state = (const float*)d_in[0];
    const float* history   = (const float*)d_in[1];
    float*       out       = (float*)d_out;

    // 1) split history fp32 -> fp16 hi/lo scratch
    prep_split<<<KTOT / 8 / 256, 256>>>(history);

    // 2) fused flash attention: K loaded once, V-fragments via movmatrix
    cudaFuncSetAttribute(attn_hmma, cudaFuncAttributeMaxDynamicSharedMemorySize, SMEM_BYTES);
    dim3 grid(Qlen / BM, Bsz);
    attn_hmma<<<grid, NT, SMEM_BYTES>>>(out_state, out);
}

// round 13
// speedup vs baseline: 1.1382x; 1.1382x over previous
#include <cuda_runtime.h>
#include <cuda_fp16.h>
#include <stdint.h>
#include <math.h>

// Problem constants (fixed by dataset)
#define Bsz  8
#define Qlen 2048
#define Klen 2048
#define Hdim 128
#define BM   64          // queries per CTA
#define BN   64          // keys per tile
#define NT   128         // 4 warps
#define NTILE (Klen / BN)

#define KTOT (Bsz * Klen * Hdim)   // 2,097,152 elements

// Pre-split history scratch (fp16 hi + residual lo), row-major [b][key][h]
__device__ __align__(16) __half g_khi[KTOT];
__device__ __align__(16) __half g_klo[KTOT];

// smem: [0,64K) K double buffer (32KB stages: hi+lo), [64K,80K) Q-hi, [80K,96K) Q-lo
#define TILE_HI_BYTES 16384
#define TILE_BYTES    32768
#define QHI_OFF       65536
#define QLO_OFF       81920
#define SMEM_BYTES    98304

#define LOG2E 1.4426950408889634f
#define ONESF16X2 0x3C003C00u     // half2(1.0, 1.0)

__device__ __forceinline__ uint32_t smem_u32(const void* p) {
    uint32_t a;
    asm("{ .reg .u64 t; cvta.to.shared.u64 t, %1; cvt.u32.u64 %0, t; }" : "=r"(a) : "l"(p));
    return a;
}
__device__ __forceinline__ uint32_t h2u(__half2 h) { return *reinterpret_cast<uint32_t*>(&h); }
__device__ __forceinline__ float ex2f(float x) {
    float y; asm("ex2.approx.ftz.f32 %0, %1;" : "=f"(y) : "f"(x)); return y;
}
__device__ __forceinline__ uint32_t ex2h2(uint32_t x) {
    uint32_t y; asm("ex2.approx.f16x2 %0, %1;" : "=r"(y) : "r"(x)); return y;
}

// fp32 pair -> fp16 hi + fp16 residual(lo), packed half2
__device__ __forceinline__ void split_h2(float x, float y, uint32_t& hi, uint32_t& lo) {
    __half2 h = __floats2half2_rn(x, y);
    float rx = x - __half2float(__low2half(h));
    float ry = y - __half2float(__high2half(h));
    __half2 l = __floats2half2_rn(rx, ry);
    hi = h2u(h); lo = h2u(l);
}

// XOR-swizzled tile offset (16B-chunk granularity): row in [0,64), bytecol in [0,256)
__device__ __forceinline__ uint32_t swz2(int row, int bytecol) {
    int ch = bytecol >> 4;
    int chs = (ch & 8) | ((ch ^ row) & 7);
    return (uint32_t)(row * 256 + (chs << 4));
}

__device__ __forceinline__ void cpa16(uint32_t dst, const void* src) {
    asm volatile("cp.async.cg.shared.global [%0], [%1], 16;" :: "r"(dst), "l"(src));
}
#define CP_COMMIT() asm volatile("cp.async.commit_group;" ::: "memory")
#define CP_WAIT0()  asm volatile("cp.async.wait_group 0;" ::: "memory")

__device__ __forceinline__ void ldsm_x4(uint32_t& r0, uint32_t& r1, uint32_t& r2, uint32_t& r3,
                                        uint32_t addr) {
    asm volatile("ldmatrix.sync.aligned.m8n8.x4.shared.b16 {%0,%1,%2,%3}, [%4];"
                 : "=r"(r0), "=r"(r1), "=r"(r2), "=r"(r3) : "r"(addr));
}
__device__ __forceinline__ void ldsm_x4_t(uint32_t& r0, uint32_t& r1, uint32_t& r2, uint32_t& r3,
                                          uint32_t addr) {
    asm volatile("ldmatrix.sync.aligned.m8n8.x4.trans.shared.b16 {%0,%1,%2,%3}, [%4];"
                 : "=r"(r0), "=r"(r1), "=r"(r2), "=r"(r3) : "r"(addr));
}
// D(16x8,f32) += A(16x16,f16) * B(16x8,f16)
__device__ __forceinline__ void mma16816(float* d, const uint32_t* a, uint32_t b0, uint32_t b1) {
    asm volatile("mma.sync.aligned.m16n8k16.row.col.f32.f16.f16.f32 "
                 "{%0,%1,%2,%3}, {%4,%5,%6,%7}, {%8,%9}, {%0,%1,%2,%3};"
                 : "+f"(d[0]), "+f"(d[1]), "+f"(d[2]), "+f"(d[3])
                 : "r"(a[0]), "r"(a[1]), "r"(a[2]), "r"(a[3]), "r"(b0), "r"(b1));
}

// ---------------- Pre-pass: split history fp32 -> fp16 hi/lo ----------------
__global__ __launch_bounds__(256)
void prep_split(const float* __restrict__ history)
{
    const size_t i = ((size_t)blockIdx.x * 256 + threadIdx.x) * 8;
    float4 a = *(const float4*)(history + i);
    float4 b = *(const float4*)(history + i + 4);
    uint32_t h[4], l[4];
    split_h2(a.x, a.y, h[0], l[0]);
    split_h2(a.z, a.w, h[1], l[1]);
    split_h2(b.x, b.y, h[2], l[2]);
    split_h2(b.z, b.w, h[3], l[3]);
    *(uint4*)(g_khi + i) = make_uint4(h[0], h[1], h[2], h[3]);
    *(uint4*)(g_klo + i) = make_uint4(l[0], l[1], l[2], l[3]);
}

// ---------------- Main attention kernel ----------------
__global__ __launch_bounds__(NT, 2)
void attn_hmma(const float* __restrict__ out_state,
               float* __restrict__ out)
{
    extern __shared__ __align__(16) char smb[];
    const uint32_t s_base = smem_u32(smb);

    const int t    = threadIdx.x;
    const int wm   = t >> 5;          // warp id = query-row group
    const int lane = t & 31;
    const int g    = lane >> 2;       // row within fragment group (0..7)
    const int tc   = lane & 3;        // col pair within group
    const int q0   = blockIdx.x * BM;
    const int b    = blockIdx.y;

    const float*  q_g  = out_state + (size_t)b * Qlen * Hdim;
    const __half* khiB = g_khi + (size_t)b * Klen * Hdim;
    const __half* kloB = g_klo + (size_t)b * Klen * Hdim;
    float*        o_g  = out + (size_t)b * Qlen * Hdim;

    // ---- Prologue A: cooperative Q tile -> tanh*log2e -> split -> smem ----
    {
        #pragma unroll
        for (int j = 0; j < 16; ++j) {
            const int idx = j * NT + t;       // 0..2047 float4s
            const int row = idx >> 5;         // 0..63
            const int c4  = idx & 31;         // float4 within row
            float4 x = *(const float4*)(q_g + (size_t)(q0 + row) * Hdim + c4 * 4);
            x.x = tanhf(x.x) * LOG2E; x.y = tanhf(x.y) * LOG2E;
            x.z = tanhf(x.z) * LOG2E; x.w = tanhf(x.w) * LOG2E;
            uint32_t h0, l0, h1, l1;
            split_h2(x.x, x.y, h0, l0);
            split_h2(x.z, x.w, h1, l1);
            const uint32_t off = swz2(row, c4 * 8) + ((c4 * 8) & 15);   // 8B-aligned
            *(uint2*)(smb + QHI_OFF + off) = make_uint2(h0, h1);
            *(uint2*)(smb + QLO_OFF + off) = make_uint2(l0, l1);
        }
    }
    __syncthreads();

    // ---- Prologue B: Q-hi A-fragments via ldsm (kept in registers all kernel) ----
    // A m16k16 .x4: lanes 0-7 rows 0-7/k0-7, 8-15 rows 8-15/k0-7, 16-23 rows 0-7/k8-15, 24-31 rows 8-15/k8-15
    const int arow = wm * 16 + ((lane >> 3) & 1) * 8 + (lane & 7);
    const int acol = (lane >> 4) * 16;        // byte offset of k-half
    uint32_t qhi[8][4];
    #pragma unroll
    for (int kk = 0; kk < 8; ++kk)
        ldsm_x4(qhi[kk][0], qhi[kk][1], qhi[kk][2], qhi[kk][3],
                s_base + QHI_OFF + swz2(arow, kk * 32 + acol));

    // O accumulator: 16 h-tiles x 4 f32 (rows g, g+8) + l-column (ones-MMA)
    float o[16][4];
    #pragma unroll
    for (int n = 0; n < 16; ++n)
        #pragma unroll
        for (int j = 0; j < 4; ++j) o[n][j] = 0.f;
    float ol[4] = {0.f, 0.f, 0.f, 0.f};

    float m0 = -INFINITY, m1 = -INFINITY;

    // ---- Prefetch tile 0 into buffer 0 ----
    {
        #pragma unroll
        for (int j = 0; j < 8; ++j) {
            const int idx = j * NT + t;        // 0..1023
            const int row = idx >> 4;
            const int ch  = idx & 15;
            const uint32_t d = s_base + swz2(row, ch << 4);
            cpa16(d,                 khiB + (size_t)row * Hdim + ch * 8);
            cpa16(d + TILE_HI_BYTES, kloB + (size_t)row * Hdim + ch * 8);
        }
        CP_COMMIT();
    }

    for (int kt = 0; kt < NTILE; ++kt) {
        CP_WAIT0();
        __syncthreads();   // tile kt visible; all warps done with the other buffer

        // ---- Prefetch tile kt+1 into the other buffer ----
        if (kt + 1 < NTILE) {
            const uint32_t sb = s_base + ((kt + 1) & 1) * TILE_BYTES;
            const __half* srcH = khiB + (size_t)(kt + 1) * BN * Hdim;
            const __half* srcL = kloB + (size_t)(kt + 1) * BN * Hdim;
            #pragma unroll
            for (int j = 0; j < 8; ++j) {
                const int idx = j * NT + t;
                const int row = idx >> 4;
                const int ch  = idx & 15;
                const uint32_t d = sb + swz2(row, ch << 4);
                cpa16(d,                 srcH + (size_t)row * Hdim + ch * 8);
                cpa16(d + TILE_HI_BYTES, srcL + (size_t)row * Hdim + ch * 8);
            }
            CP_COMMIT();
        }

        const uint32_t s_hi = s_base + (kt & 1) * TILE_BYTES;
        const uint32_t s_lo = s_hi + TILE_HI_BYTES;

        // ---- QK^T: S (16x64 per warp), 3-pass split; Q-lo A-frags from smem ----
        float s[8][4];
        #pragma unroll
        for (int n = 0; n < 8; ++n)
            #pragma unroll
            for (int j = 0; j < 4; ++j) s[n][j] = 0.f;

        #pragma unroll
        for (int kk = 0; kk < 8; ++kk) {
            uint32_t ql[4];
            ldsm_x4(ql[0], ql[1], ql[2], ql[3],
                    s_base + QLO_OFF + swz2(arow, kk * 32 + acol));
            uint32_t bh[4][4], bl[4][4];
            #pragma unroll
            for (int np = 0; np < 4; ++np) {
                const int row = np * 16 + (lane & 7) + ((lane >> 4) << 3);
                const int col = kk * 32 + ((lane >> 3) & 1) * 16;   // bytes
                const uint32_t a = swz2(row, col);
                ldsm_x4(bh[np][0], bh[np][1], bh[np][2], bh[np][3], s_hi + a);
                ldsm_x4(bl[np][0], bl[np][1], bl[np][2], bl[np][3], s_lo + a);
            }
            #pragma unroll
            for (int n = 0; n < 8; ++n)
                mma16816(s[n], qhi[kk], bh[n >> 1][(n & 1) * 2], bh[n >> 1][(n & 1) * 2 + 1]);
            #pragma unroll
            for (int n = 0; n < 8; ++n)
                mma16816(s[n], qhi[kk], bl[n >> 1][(n & 1) * 2], bl[n >> 1][(n & 1) * 2 + 1]);
            #pragma unroll
            for (int n = 0; n < 8; ++n)
                mma16816(s[n], ql, bh[n >> 1][(n & 1) * 2], bh[n >> 1][(n & 1) * 2 + 1]);
        }

        // ---- Online max (warp-local); l via ones-MMA ----
        float t0 = -INFINITY, t1 = -INFINITY;
        #pragma unroll
        for (int n = 0; n < 8; ++n) {
            t0 = fmaxf(t0, fmaxf(s[n][0], s[n][1]));
            t1 = fmaxf(t1, fmaxf(s[n][2], s[n][3]));
        }
        t0 = fmaxf(t0, __shfl_xor_sync(0xffffffffu, t0, 1));
        t0 = fmaxf(t0, __shfl_xor_sync(0xffffffffu, t0, 2));
        t1 = fmaxf(t1, __shfl_xor_sync(0xffffffffu, t1, 1));
        t1 = fmaxf(t1, __shfl_xor_sync(0xffffffffu, t1, 2));

        const float mn0 = fmaxf(m0, t0), mn1 = fmaxf(m1, t1);
        const bool updated = (mn0 != m0) | (mn1 != m1);
        const bool any_up  = __any_sync(0xffffffffu, updated);
        const float al0 = ex2f(m0 - mn0), al1 = ex2f(m1 - mn1);
        m0 = mn0; m1 = mn1;

        // ---- p = 2^(s-m) via packed fp16 ex2 -> pa fragments directly ----
        uint32_t pa[4][4];
        #pragma unroll
        for (int n = 0; n < 8; ++n) {
            uint32_t ua = h2u(__floats2half2_rn(s[n][0] - mn0, s[n][1] - mn0));
            uint32_t ub = h2u(__floats2half2_rn(s[n][2] - mn1, s[n][3] - mn1));
            pa[n >> 1][(n & 1) * 2]     = ex2h2(ua);
            pa[n >> 1][(n & 1) * 2 + 1] = ex2h2(ub);
        }

        if (any_up) {
            #pragma unroll
            for (int n = 0; n < 16; ++n) {
                o[n][0] *= al0; o[n][1] *= al0;
                o[n][2] *= al1; o[n][3] *= al1;
            }
            ol[0] *= al0; ol[1] *= al0; ol[2] *= al1; ol[3] *= al1;
        }

        // ---- PV: O += P * V (V = same smem bytes as K-hi, via ldmatrix.trans) ----
        #pragma unroll
        for (int kg = 0; kg < 4; ++kg) {
            #pragma unroll
            for (int hp = 0; hp < 8; ++hp) {
                const int row = kg * 16 + (lane & 7) + (((lane >> 3) & 1) << 3);
                const int col = hp * 32 + ((lane >> 4) & 1) * 16;
                uint32_t r0, r1, r2, r3;
                ldsm_x4_t(r0, r1, r2, r3, s_hi + swz2(row, col));
                mma16816(o[2*hp],     pa[kg], r0, r1);
                mma16816(o[2*hp + 1], pa[kg], r2, r3);
            }
            mma16816(ol, pa[kg], ONESF16X2, ONESF16X2);   // row sums -> l
        }
    }

    // ---- Epilogue: normalize by l and store ----
    const float inv0 = 1.0f / ol[0];
    const float inv1 = 1.0f / ol[2];
    float* ob = o_g + (size_t)(q0 + wm * 16 + g) * Hdim;
    #pragma unroll
    for (int n = 0; n < 16; ++n) {
        const int h = n * 8 + tc * 2;
        *(float2*)(ob + h)            = make_float2(o[n][0] * inv0, o[n][1] * inv0);
        *(float2*)(ob + 8 * Hdim + h) = make_float2(o[n][2] * inv1, o[n][3] * inv1);
    }
}

extern "C" void kernel_launch(void* const* d_in, const int* in_sizes, int n_in,
                              void* d_out, int out_size)
{
    const float* out_state = (const float*)d_in[0];
    const float* history   = (const float*)d_in[1];
    float*       out       = (float*)d_out;

    // 1) split history fp32 -> fp16 hi/lo scratch
    prep_split<<<KTOT / 8 / 256, 256>>>(history);

    // 2) fused flash attention; Q in smem to free registers for ptxas pipelining
    cudaFuncSetAttribute(attn_hmma, cudaFuncAttributeMaxDynamicSharedMemorySize, SMEM_BYTES);
    dim3 grid(Qlen / BM, Bsz);
    attn_hmma<<<grid, NT, SMEM_BYTES>>>(out_state, out);
}

// round 14
// speedup vs baseline: 1.4517x; 1.2754x over previous
#include <cuda_runtime.h>
#include <cuda_fp16.h>
#include <stdint.h>
#include <math.h>

// Problem constants (fixed by dataset)
#define Bsz  8
#define Qlen 2048
#define Klen 2048
#define Hdim 128
#define BM   64          // queries per CTA
#define BN   64          // keys per tile
#define NT   128         // 4 warps
#define NTILE (Klen / BN)

#define KTOT (Bsz * Klen * Hdim)   // 2,097,152 elements

// Pre-rounded history (fp16), row-major [b][key][h]. QK uses S = (Qhi+Qlo)·Khi,
// PV uses the same Khi bytes as V — one tile, loaded once.
__device__ __align__(16) __half g_khi[KTOT];

// smem tile: 64 rows x 128 fp16 = 16KB; double buffered = 32KB
#define TILE_BYTES 16384
#define SMEM_BYTES (2 * TILE_BYTES)

#define LOG2E 1.4426950408889634f
#define ONESF16X2 0x3C003C00u     // half2(1.0, 1.0)

__device__ __forceinline__ uint32_t smem_u32(const void* p) {
    uint32_t a;
    asm("{ .reg .u64 t; cvta.to.shared.u64 t, %1; cvt.u32.u64 %0, t; }" : "=r"(a) : "l"(p));
    return a;
}
__device__ __forceinline__ uint32_t h2u(__half2 h) { return *reinterpret_cast<uint32_t*>(&h); }
__device__ __forceinline__ float ex2f(float x) {
    float y; asm("ex2.approx.ftz.f32 %0, %1;" : "=f"(y) : "f"(x)); return y;
}
__device__ __forceinline__ uint32_t ex2h2(uint32_t x) {
    uint32_t y; asm("ex2.approx.f16x2 %0, %1;" : "=r"(y) : "r"(x)); return y;
}

// fp32 pair -> fp16 hi + fp16 residual(lo), packed half2
__device__ __forceinline__ void split_h2(float x, float y, uint32_t& hi, uint32_t& lo) {
    __half2 h = __floats2half2_rn(x, y);
    float rx = x - __half2float(__low2half(h));
    float ry = y - __half2float(__high2half(h));
    __half2 l = __floats2half2_rn(rx, ry);
    hi = h2u(h); lo = h2u(l);
}

// XOR-swizzled tile offset: row in [0,64), bytecol in [0,256)
__device__ __forceinline__ uint32_t swz2(int row, int bytecol) {
    int ch = bytecol >> 4;
    int chs = (ch & 8) | ((ch ^ row) & 7);
    return (uint32_t)(row * 256 + (chs << 4));
}

__device__ __forceinline__ void cpa16(uint32_t dst, const void* src) {
    asm volatile("cp.async.cg.shared.global [%0], [%1], 16;" :: "r"(dst), "l"(src));
}
#define CP_COMMIT() asm volatile("cp.async.commit_group;" ::: "memory")
#define CP_WAIT0()  asm volatile("cp.async.wait_group 0;" ::: "memory")

__device__ __forceinline__ void ldsm_x4(uint32_t& r0, uint32_t& r1, uint32_t& r2, uint32_t& r3,
                                        uint32_t addr) {
    asm volatile("ldmatrix.sync.aligned.m8n8.x4.shared.b16 {%0,%1,%2,%3}, [%4];"
                 : "=r"(r0), "=r"(r1), "=r"(r2), "=r"(r3) : "r"(addr));
}
__device__ __forceinline__ void ldsm_x4_t(uint32_t& r0, uint32_t& r1, uint32_t& r2, uint32_t& r3,
                                          uint32_t addr) {
    asm volatile("ldmatrix.sync.aligned.m8n8.x4.trans.shared.b16 {%0,%1,%2,%3}, [%4];"
                 : "=r"(r0), "=r"(r1), "=r"(r2), "=r"(r3) : "r"(addr));
}
// D(16x8,f32) += A(16x16,f16) * B(16x8,f16)
__device__ __forceinline__ void mma16816(float* d, const uint32_t* a, uint32_t b0, uint32_t b1) {
    asm volatile("mma.sync.aligned.m16n8k16.row.col.f32.f16.f16.f32 "
                 "{%0,%1,%2,%3}, {%4,%5,%6,%7}, {%8,%9}, {%0,%1,%2,%3};"
                 : "+f"(d[0]), "+f"(d[1]), "+f"(d[2]), "+f"(d[3])
                 : "r"(a[0]), "r"(a[1]), "r"(a[2]), "r"(a[3]), "r"(b0), "r"(b1));
}

// ---------------- Pre-pass: round history fp32 -> fp16 ----------------
__global__ __launch_bounds__(256)
void prep_round(const float* __restrict__ history)
{
    const size_t i = ((size_t)blockIdx.x * 256 + threadIdx.x) * 8;
    float4 a = *(const float4*)(history + i);
    float4 b = *(const float4*)(history + i + 4);
    uint32_t h[4];
    h[0] = h2u(__floats2half2_rn(a.x, a.y));
    h[1] = h2u(__floats2half2_rn(a.z, a.w));
    h[2] = h2u(__floats2half2_rn(b.x, b.y));
    h[3] = h2u(__floats2half2_rn(b.z, b.w));
    *(uint4*)(g_khi + i) = make_uint4(h[0], h[1], h[2], h[3]);
}

// ---------------- Main attention kernel ----------------
__global__ __launch_bounds__(NT, 2)
void attn_hmma(const float* __restrict__ out_state,
               float* __restrict__ out)
{
    extern __shared__ __align__(16) char smb[];
    const uint32_t s_base = smem_u32(smb);

    const int t    = threadIdx.x;
    const int wm   = t >> 5;          // warp id = query-row group
    const int lane = t & 31;
    const int g    = lane >> 2;       // row within fragment group (0..7)
    const int tc   = lane & 3;        // col pair within group
    const int q0   = blockIdx.x * BM;
    const int b    = blockIdx.y;

    const float*  q_g  = out_state + (size_t)b * Qlen * Hdim;
    const __half* khiB = g_khi + (size_t)b * Klen * Hdim;
    float*        o_g  = out + (size_t)b * Qlen * Hdim;

    // ---- Q A-fragments: tanh * log2e, split fp16 hi/lo (both kept in regs) ----
    uint32_t qhi[8][4], qlo[8][4];
    {
        const float* qb = q_g + (size_t)(q0 + wm * 16 + g) * Hdim;
        #pragma unroll
        for (int kk = 0; kk < 8; ++kk) {
            const int h0 = kk * 16 + tc * 2;
            float2 x00 = *(const float2*)(qb + h0);
            float2 x10 = *(const float2*)(qb + 8 * Hdim + h0);
            float2 x01 = *(const float2*)(qb + h0 + 8);
            float2 x11 = *(const float2*)(qb + 8 * Hdim + h0 + 8);
            x00.x = tanhf(x00.x) * LOG2E; x00.y = tanhf(x00.y) * LOG2E;
            x10.x = tanhf(x10.x) * LOG2E; x10.y = tanhf(x10.y) * LOG2E;
            x01.x = tanhf(x01.x) * LOG2E; x01.y = tanhf(x01.y) * LOG2E;
            x11.x = tanhf(x11.x) * LOG2E; x11.y = tanhf(x11.y) * LOG2E;
            split_h2(x00.x, x00.y, qhi[kk][0], qlo[kk][0]);
            split_h2(x10.x, x10.y, qhi[kk][1], qlo[kk][1]);
            split_h2(x01.x, x01.y, qhi[kk][2], qlo[kk][2]);
            split_h2(x11.x, x11.y, qhi[kk][3], qlo[kk][3]);
        }
    }

    // O accumulator: 16 h-tiles x 4 f32 (rows g, g+8) + l-column (ones-MMA)
    float o[16][4];
    #pragma unroll
    for (int n = 0; n < 16; ++n)
        #pragma unroll
        for (int j = 0; j < 4; ++j) o[n][j] = 0.f;
    float ol[4] = {0.f, 0.f, 0.f, 0.f};

    float m0 = -INFINITY, m1 = -INFINITY;

    // ---- Prefetch tile 0 into buffer 0 (16KB: 1024 chunks, 8 per thread) ----
    {
        #pragma unroll
        for (int j = 0; j < 8; ++j) {
            const int idx = j * NT + t;        // 0..1023
            const int row = idx >> 4;
            const int ch  = idx & 15;
            cpa16(s_base + swz2(row, ch << 4), khiB + (size_t)row * Hdim + ch * 8);
        }
        CP_COMMIT();
    }

    for (int kt = 0; kt < NTILE; ++kt) {
        CP_WAIT0();
        __syncthreads();   // tile kt visible; all warps done with the other buffer

        // ---- Prefetch tile kt+1 into the other buffer ----
        if (kt + 1 < NTILE) {
            const uint32_t sb = s_base + ((kt + 1) & 1) * TILE_BYTES;
            const __half* srcH = khiB + (size_t)(kt + 1) * BN * Hdim;
            #pragma unroll
            for (int j = 0; j < 8; ++j) {
                const int idx = j * NT + t;
                const int row = idx >> 4;
                const int ch  = idx & 15;
                cpa16(sb + swz2(row, ch << 4), srcH + (size_t)row * Hdim + ch * 8);
            }
            CP_COMMIT();
        }

        const uint32_t s_hi = s_base + (kt & 1) * TILE_BYTES;

        // ---- QK^T: S = (Qhi + Qlo) . Khi  (2 passes, one K tile) ----
        float s[8][4];
        #pragma unroll
        for (int n = 0; n < 8; ++n)
            #pragma unroll
            for (int j = 0; j < 4; ++j) s[n][j] = 0.f;

        #pragma unroll
        for (int kk = 0; kk < 8; ++kk) {
            uint32_t bh[4][4];
            #pragma unroll
            for (int np = 0; np < 4; ++np) {
                const int row = np * 16 + (lane & 7) + ((lane >> 4) << 3);
                const int col = kk * 32 + ((lane >> 3) & 1) * 16;   // bytes
                ldsm_x4(bh[np][0], bh[np][1], bh[np][2], bh[np][3], s_hi + swz2(row, col));
            }
            #pragma unroll
            for (int n = 0; n < 8; ++n)
                mma16816(s[n], qhi[kk], bh[n >> 1][(n & 1) * 2], bh[n >> 1][(n & 1) * 2 + 1]);
            #pragma unroll
            for (int n = 0; n < 8; ++n)
                mma16816(s[n], qlo[kk], bh[n >> 1][(n & 1) * 2], bh[n >> 1][(n & 1) * 2 + 1]);
        }

        // ---- Online max (warp-local); l via ones-MMA ----
        float t0 = -INFINITY, t1 = -INFINITY;
        #pragma unroll
        for (int n = 0; n < 8; ++n) {
            t0 = fmaxf(t0, fmaxf(s[n][0], s[n][1]));
            t1 = fmaxf(t1, fmaxf(s[n][2], s[n][3]));
        }
        t0 = fmaxf(t0, __shfl_xor_sync(0xffffffffu, t0, 1));
        t0 = fmaxf(t0, __shfl_xor_sync(0xffffffffu, t0, 2));
        t1 = fmaxf(t1, __shfl_xor_sync(0xffffffffu, t1, 1));
        t1 = fmaxf(t1, __shfl_xor_sync(0xffffffffu, t1, 2));

        const float mn0 = fmaxf(m0, t0), mn1 = fmaxf(m1, t1);
        const bool updated = (mn0 != m0) | (mn1 != m1);
        const bool any_up  = __any_sync(0xffffffffu, updated);
        const float al0 = ex2f(m0 - mn0), al1 = ex2f(m1 - mn1);
        m0 = mn0; m1 = mn1;

        // ---- p = 2^(s-m) via packed fp16 ex2 -> pa fragments directly ----
        uint32_t pa[4][4];
        #pragma unroll
        for (int n = 0; n < 8; ++n) {
            uint32_t ua = h2u(__floats2half2_rn(s[n][0] - mn0, s[n][1] - mn0));
            uint32_t ub = h2u(__floats2half2_rn(s[n][2] - mn1, s[n][3] - mn1));
            pa[n >> 1][(n & 1) * 2]     = ex2h2(ua);
            pa[n >> 1][(n & 1) * 2 + 1] = ex2h2(ub);
        }

        if (any_up) {
            #pragma unroll
            for (int n = 0; n < 16; ++n) {
                o[n][0] *= al0; o[n][1] *= al0;
                o[n][2] *= al1; o[n][3] *= al1;
            }
            ol[0] *= al0; ol[1] *= al0; ol[2] *= al1; ol[3] *= al1;
        }

        // ---- PV: O += P * V (V = same smem bytes, via ldmatrix.trans) ----
        #pragma unroll
        for (int kg = 0; kg < 4; ++kg) {
            #pragma unroll
            for (int hp = 0; hp < 8; ++hp) {
                const int row = kg * 16 + (lane & 7) + (((lane >> 3) & 1) << 3);
                const int col = hp * 32 + ((lane >> 4) & 1) * 16;
                uint32_t r0, r1, r2, r3;
                ldsm_x4_t(r0, r1, r2, r3, s_hi + swz2(row, col));
                mma16816(o[2*hp],     pa[kg], r0, r1);
                mma16816(o[2*hp + 1], pa[kg], r2, r3);
            }
            mma16816(ol, pa[kg], ONESF16X2, ONESF16X2);   // row sums -> l
        }
    }

    // ---- Epilogue: normalize by l and store ----
    const float inv0 = 1.0f / ol[0];
    const float inv1 = 1.0f / ol[2];
    float* ob = o_g + (size_t)(q0 + wm * 16 + g) * Hdim;
    #pragma unroll
    for (int n = 0; n < 16; ++n) {
        const int h = n * 8 + tc * 2;
        *(float2*)(ob + h)            = make_float2(o[n][0] * inv0, o[n][1] * inv0);
        *(float2*)(ob + 8 * Hdim + h) = make_float2(o[n][2] * inv1, o[n][3] * inv1);
    }
}

extern "C" void kernel_launch(void* const* d_in, const int* in_sizes, int n_in,
                              void* d_out, int out_size)
{
    const float* out_state = (const float*)d_in[0];
    const float* history   = (const float*)d_in[1];
    float*       out       = (float*)d_out;

    // 1) round history fp32 -> fp16
    prep_round<<<KTOT / 8 / 256, 256>>>(history);

    // 2) fused flash attention: 2-pass QK (split Q, fp16 K) + fp16 PV
    cudaFuncSetAttribute(attn_hmma, cudaFuncAttributeMaxDynamicSharedMemorySize, SMEM_BYTES);
    dim3 grid(Qlen / BM, Bsz);
    attn_hmma<<<grid, NT, SMEM_BYTES>>>(out_state, out);
}